// round 13
// baseline (speedup 1.0000x reference)
#include <cuda_runtime.h>
#include <cuda_bf16.h>
#include <cuda_fp16.h>
#include <stdint.h>

#define NMAX 100032
#define FDIM 512
#define CDIM 64
#define ALPHA 0.2f
#define BCAP 128

__device__ __align__(256) float  g_h0   [(size_t)NMAX * CDIM];
__device__ __align__(256) __half g_msg16[(size_t)NMAX * CDIM];
__device__ int   g_cnt_in[NMAX];
__device__ int   g_cnt_out[NMAX];
__device__ __align__(16) int g_ebuf[(size_t)NMAX * BCAP];

__device__ __align__(16) uint16_t g_wb_hi[8 * 64 * 72];
__device__ __align__(16) uint16_t g_wb_lo[8 * 64 * 72];

// ---------------------------------------------------------------------------
// helpers
// ---------------------------------------------------------------------------
__device__ __forceinline__ uint32_t smem_u32(const void* p) {
    uint32_t a;
    asm("{ .reg .u64 t; cvta.to.shared.u64 t, %1; cvt.u32.u64 %0, t; }"
        : "=r"(a) : "l"(p));
    return a;
}
__device__ __forceinline__ float trunc_bf(float x) {
    return __uint_as_float(__float_as_uint(x) & 0xFFFF0000u);
}
__device__ __forceinline__ uint32_t pack_lo2(float e0, float e1) {
    float r0 = e0 - trunc_bf(e0);
    float r1 = e1 - trunc_bf(e1);
    uint32_t d;
    asm("cvt.rn.bf16x2.f32 %0, %1, %2;" : "=r"(d) : "f"(r1), "f"(r0));
    return d;
}
__device__ __forceinline__ void mma_bf16(float* d, const uint32_t* a,
                                         uint32_t b0, uint32_t b1) {
    asm volatile(
        "mma.sync.aligned.m16n8k16.row.col.f32.bf16.bf16.f32 "
        "{%0,%1,%2,%3}, {%4,%5,%6,%7}, {%8,%9}, {%0,%1,%2,%3};"
        : "+f"(d[0]), "+f"(d[1]), "+f"(d[2]), "+f"(d[3])
        : "r"(a[0]), "r"(a[1]), "r"(a[2]), "r"(a[3]), "r"(b0), "r"(b1));
}
__device__ __forceinline__ void cp_async16(uint32_t dst, const void* src) {
    asm volatile("cp.async.ca.shared.global [%0], [%1], 16;"
                 :: "r"(dst), "l"(src) : "memory");
}

// ---------------------------------------------------------------------------
// 1) prep: zero counters + W -> bf16 hi/lo fragment images (fused)
// ---------------------------------------------------------------------------
__global__ void prep_kernel(const float* __restrict__ W, int N) {
    int idx = blockIdx.x * blockDim.x + threadIdx.x;
    if (idx < N) { g_cnt_in[idx] = 0; g_cnt_out[idx] = 0; }
    if (idx < CDIM * FDIM) {
        int n = idx >> 9;
        int k = idx & 511;
        float w = W[idx];
        uint32_t wb = __float_as_uint(w);
        uint16_t hi = (uint16_t)(wb >> 16);
        float lo = w - __uint_as_float(wb & 0xFFFF0000u);
        __nv_bfloat16 lob = __float2bfloat16_rn(lo);

        int ch = k >> 6;
        int kl = k & 63;
        int ks = kl >> 4;
        int jj = kl & 15;
        int p = (jj < 8) ? ((jj >> 1) * 4 + (jj & 1))
                         : (((jj - 8) >> 1) * 4 + 2 + (jj & 1));
        int off = ch * (64 * 72) + n * 72 + ks * 16 + p;
        g_wb_hi[off] = hi;
        g_wb_lo[off] = *reinterpret_cast<uint16_t*>(&lob);
    }
}

// ---------------------------------------------------------------------------
// 2) fill: both degrees + bucket by dst, 4 edges/thread
// ---------------------------------------------------------------------------
__global__ void fill_kernel(const int* __restrict__ src,
                            const int* __restrict__ dst, int E, int N) {
    int t = blockIdx.x * blockDim.x + threadIdx.x;
    int base = t * 4;
    if (base + 3 < E) {
        int4 s4 = *reinterpret_cast<const int4*>(src + base);
        int4 d4 = *reinterpret_cast<const int4*>(dst + base);
        atomicAdd(&g_cnt_out[s4.x], 1);
        atomicAdd(&g_cnt_out[s4.y], 1);
        atomicAdd(&g_cnt_out[s4.z], 1);
        atomicAdd(&g_cnt_out[s4.w], 1);
        int p0 = atomicAdd(&g_cnt_in[d4.x], 1);
        int p1 = atomicAdd(&g_cnt_in[d4.y], 1);
        int p2 = atomicAdd(&g_cnt_in[d4.z], 1);
        int p3 = atomicAdd(&g_cnt_in[d4.w], 1);
        if (p0 < BCAP) g_ebuf[(size_t)d4.x * BCAP + p0] = s4.x;
        if (p1 < BCAP) g_ebuf[(size_t)d4.y * BCAP + p1] = s4.y;
        if (p2 < BCAP) g_ebuf[(size_t)d4.z * BCAP + p2] = s4.z;
        if (p3 < BCAP) g_ebuf[(size_t)d4.w * BCAP + p3] = s4.w;
    } else {
        for (int k = 0; k < 4; k++) {
            int e = base + k;
            if (e >= E) break;
            int s = src[e], d = dst[e];
            if ((unsigned)s >= (unsigned)N || (unsigned)d >= (unsigned)N) continue;
            atomicAdd(&g_cnt_out[s], 1);
            int pos = atomicAdd(&g_cnt_in[d], 1);
            if (pos < BCAP) g_ebuf[(size_t)d * BCAP + pos] = s;
        }
    }
}

// ---------------------------------------------------------------------------
// 3) mma.sync GEMM, BM=64, occ 3: h0 = X@W^T + b
//    dyn smem: A buf b @ b*18432 (64 rows x 288 B)
//              B hi  b @ 36864 + b*18432 ; B lo at +9216
// ---------------------------------------------------------------------------
#define BM 64
#define A_STRIDE_B 288
#define B_STRIDE_B 144
#define A_BUF_B 18432
#define B_BUF_B 18432
#define GEMM_SMEM 73728

__device__ __forceinline__ void issue_chunk(char* smem, const float* X,
                                            int brow, int N, int ch, int buf,
                                            int tid) {
    char* adst = smem + buf * A_BUF_B;
    int k0 = ch * 64;
#pragma unroll
    for (int i = 0; i < 8; i++) {
        int q = tid + i * 128;          // 0..1023 (64 rows x 16 segs)
        int r = q >> 4, s = q & 15;
        int row = brow + r;
        if (row >= N) row = N - 1;
        const float* src = X + (size_t)row * FDIM + k0 + s * 4;
        cp_async16(smem_u32(adst + r * A_STRIDE_B + s * 16), src);
    }
    const char* bsrc_h = reinterpret_cast<const char*>(g_wb_hi) + ch * 9216;
    const char* bsrc_l = reinterpret_cast<const char*>(g_wb_lo) + ch * 9216;
    char* bh = smem + 36864 + buf * B_BUF_B;
    char* bl = bh + 9216;
#pragma unroll
    for (int i = 0; i < 5; i++) {
        int q = tid + i * 128;
        if (q < 576) {
            cp_async16(smem_u32(bh + q * 16), bsrc_h + q * 16);
            cp_async16(smem_u32(bl + q * 16), bsrc_l + q * 16);
        }
    }
}

__global__ __launch_bounds__(128, 3)
void gemm_mma(const float* __restrict__ X, const float* __restrict__ bias, int N) {
    extern __shared__ __align__(16) char smem[];
    __shared__ float s_bias[CDIM];

    int tid = threadIdx.x;
    int wid = tid >> 5;
    int lane = tid & 31;
    int gr = lane >> 2;
    int tg = lane & 3;
    int brow = blockIdx.x * BM;

    if (tid < CDIM) s_bias[tid] = bias[tid];

    float acc[8][4];
#pragma unroll
    for (int t = 0; t < 8; t++)
#pragma unroll
        for (int j = 0; j < 4; j++) acc[t][j] = 0.f;

    issue_chunk(smem, X, brow, N, 0, 0, tid);
    asm volatile("cp.async.commit_group;" ::: "memory");
    issue_chunk(smem, X, brow, N, 1, 1, tid);
    asm volatile("cp.async.commit_group;" ::: "memory");

    for (int c = 0; c < 8; c++) {
        int b = c & 1;
        asm volatile("cp.async.wait_group 1;" ::: "memory");
        __syncthreads();

        const char* ab = smem + b * A_BUF_B;
        const char* bh = smem + 36864 + b * B_BUF_B;
        const char* bl = bh + 9216;

#pragma unroll
        for (int ks = 0; ks < 4; ks++) {
            uint32_t ah[4], al[4];
            {
                int r0 = wid * 16 + gr;     // warp covers 16 rows
                const char* base = ab + r0 * A_STRIDE_B + (ks * 16 + tg * 2) * 4;
                float2 x00 = *reinterpret_cast<const float2*>(base);
                float2 x01 = *reinterpret_cast<const float2*>(base + 32);
                float2 x10 = *reinterpret_cast<const float2*>(base + 8 * A_STRIDE_B);
                float2 x11 = *reinterpret_cast<const float2*>(base + 8 * A_STRIDE_B + 32);
                ah[0] = __byte_perm(__float_as_uint(x00.x), __float_as_uint(x00.y), 0x7632);
                ah[1] = __byte_perm(__float_as_uint(x10.x), __float_as_uint(x10.y), 0x7632);
                ah[2] = __byte_perm(__float_as_uint(x01.x), __float_as_uint(x01.y), 0x7632);
                ah[3] = __byte_perm(__float_as_uint(x11.x), __float_as_uint(x11.y), 0x7632);
                al[0] = pack_lo2(x00.x, x00.y);
                al[1] = pack_lo2(x10.x, x10.y);
                al[2] = pack_lo2(x01.x, x01.y);
                al[3] = pack_lo2(x11.x, x11.y);
            }
#pragma unroll
            for (int t = 0; t < 8; t++) {
                int n = t * 8 + gr;
                const char* bp = bh + n * B_STRIDE_B + ks * 32 + tg * 8;
                const char* lp = bl + n * B_STRIDE_B + ks * 32 + tg * 8;
                uint2 bhv = *reinterpret_cast<const uint2*>(bp);
                uint2 blv = *reinterpret_cast<const uint2*>(lp);
                mma_bf16(acc[t], ah, bhv.x, bhv.y);
                mma_bf16(acc[t], ah, blv.x, blv.y);
                mma_bf16(acc[t], al, bhv.x, bhv.y);
            }
        }
        __syncthreads();
        if (c + 2 < 8) issue_chunk(smem, X, brow, N, c + 2, b, tid);
        asm volatile("cp.async.commit_group;" ::: "memory");
    }

    {
        int row0 = brow + wid * 16 + gr;
        int row1 = row0 + 8;
#pragma unroll
        for (int t = 0; t < 8; t++) {
            int col = t * 8 + tg * 2;
            float b0 = s_bias[col], b1 = s_bias[col + 1];
            if (row0 < N) {
                *reinterpret_cast<float2*>(g_h0 + (size_t)row0 * CDIM + col) =
                    make_float2(acc[t][0] + b0, acc[t][1] + b1);
            }
            if (row1 < N) {
                *reinterpret_cast<float2*>(g_h0 + (size_t)row1 * CDIM + col) =
                    make_float2(acc[t][2] + b0, acc[t][3] + b1);
            }
        }
    }
}

// ---------------------------------------------------------------------------
// 4) msg16 = fp16(h0 * rsqrt(max(cnt_out,1)))
// ---------------------------------------------------------------------------
__global__ void msg_kernel(int N) {
    int i = blockIdx.x * blockDim.x + threadIdx.x;
    int total = N * (CDIM / 4);
    if (i >= total) return;
    float ns = rsqrtf(fmaxf((float)g_cnt_out[i >> 4], 1.0f));
    float4 h = reinterpret_cast<const float4*>(g_h0)[i];
    __half2 p0 = __floats2half2_rn(h.x * ns, h.y * ns);
    __half2 p1 = __floats2half2_rn(h.z * ns, h.w * ns);
    uint2 v;
    v.x = *reinterpret_cast<uint32_t*>(&p0);
    v.y = *reinterpret_cast<uint32_t*>(&p1);
    reinterpret_cast<uint2*>(g_msg16)[i] = v;
}

// ---------------------------------------------------------------------------
// 5) gather + blend: warp per dst node (R10 known-good structure)
// ---------------------------------------------------------------------------
__global__ __launch_bounds__(256)
void gather_kernel(float* __restrict__ out, int N) {
    int gw = (blockIdx.x * blockDim.x + threadIdx.x) >> 5;
    if (gw >= N) return;
    int lane = threadIdx.x & 31;

    int cnt = g_cnt_in[gw];
    int m_tot = cnt < BCAP ? cnt : BCAP;
    const int* bucket = g_ebuf + (size_t)gw * BCAP;
    int co = lane * 2;

    float a0x = 0.f, a0y = 0.f, a1x = 0.f, a1y = 0.f;
    float a2x = 0.f, a2y = 0.f, a3x = 0.f, a3y = 0.f;

    for (int j0 = 0; j0 < m_tot; j0 += 32) {
        int m = m_tot - j0;
        if (m > 32) m = 32;
        int myidx = 0;
        if (lane < m) myidx = __ldg(&bucket[j0 + lane]);

        int jj = 0;
        for (; jj + 8 <= m; jj += 8) {
            int i0 = __shfl_sync(~0u, myidx, jj + 0);
            int i1 = __shfl_sync(~0u, myidx, jj + 1);
            int i2 = __shfl_sync(~0u, myidx, jj + 2);
            int i3 = __shfl_sync(~0u, myidx, jj + 3);
            int i4 = __shfl_sync(~0u, myidx, jj + 4);
            int i5 = __shfl_sync(~0u, myidx, jj + 5);
            int i6 = __shfl_sync(~0u, myidx, jj + 6);
            int i7 = __shfl_sync(~0u, myidx, jj + 7);
            __half2 h0 = *reinterpret_cast<const __half2*>(g_msg16 + (size_t)i0 * CDIM + co);
            __half2 h1 = *reinterpret_cast<const __half2*>(g_msg16 + (size_t)i1 * CDIM + co);
            __half2 h2 = *reinterpret_cast<const __half2*>(g_msg16 + (size_t)i2 * CDIM + co);
            __half2 h3 = *reinterpret_cast<const __half2*>(g_msg16 + (size_t)i3 * CDIM + co);
            __half2 h4 = *reinterpret_cast<const __half2*>(g_msg16 + (size_t)i4 * CDIM + co);
            __half2 h5 = *reinterpret_cast<const __half2*>(g_msg16 + (size_t)i5 * CDIM + co);
            __half2 h6 = *reinterpret_cast<const __half2*>(g_msg16 + (size_t)i6 * CDIM + co);
            __half2 h7 = *reinterpret_cast<const __half2*>(g_msg16 + (size_t)i7 * CDIM + co);
            float2 v0 = __half22float2(h0), v1 = __half22float2(h1);
            float2 v2 = __half22float2(h2), v3 = __half22float2(h3);
            float2 v4 = __half22float2(h4), v5 = __half22float2(h5);
            float2 v6 = __half22float2(h6), v7 = __half22float2(h7);
            a0x += v0.x; a0y += v0.y; a1x += v1.x; a1y += v1.y;
            a2x += v2.x; a2y += v2.y; a3x += v3.x; a3y += v3.y;
            a0x += v4.x; a0y += v4.y; a1x += v5.x; a1y += v5.y;
            a2x += v6.x; a2y += v6.y; a3x += v7.x; a3y += v7.y;
        }
        for (; jj < m; jj++) {
            int i0 = __shfl_sync(~0u, myidx, jj);
            float2 v = __half22float2(
                *reinterpret_cast<const __half2*>(g_msg16 + (size_t)i0 * CDIM + co));
            a0x += v.x; a0y += v.y;
        }
    }
    float sx = (a0x + a1x) + (a2x + a3x);
    float sy = (a0y + a1y) + (a2y + a3y);

    float ndv = rsqrtf(fmaxf((float)cnt, 1.0f));
    float2 h = *reinterpret_cast<const float2*>(g_h0 + (size_t)gw * CDIM + co);
    float2 r;
    r.x = (1.0f - ALPHA) * ndv * sx + ALPHA * h.x;
    r.y = (1.0f - ALPHA) * ndv * sy + ALPHA * h.y;
    *reinterpret_cast<float2*>(out + (size_t)gw * CDIM + co) = r;
}

// ---------------------------------------------------------------------------
// launch
// ---------------------------------------------------------------------------
extern "C" void kernel_launch(void* const* d_in, const int* in_sizes, int n_in,
                              void* d_out, int out_size) {
    const float* X    = (const float*)d_in[0];
    const float* W    = (const float*)d_in[1];
    const float* bias = (const float*)d_in[2];
    const int*   src  = (const int*)d_in[3];
    const int*   dst  = (const int*)d_in[4];

    int N = in_sizes[0] / FDIM;
    int E = in_sizes[3];
    float* out = (float*)d_out;

    static cudaStream_t s1 = nullptr;
    static cudaEvent_t evF = nullptr, evB = nullptr, evJ = nullptr;
    static bool init_done = false;
    if (!init_done) {
        cudaFuncSetAttribute(gemm_mma, cudaFuncAttributeMaxDynamicSharedMemorySize,
                             GEMM_SMEM);
        cudaStreamCreateWithFlags(&s1, cudaStreamNonBlocking);
        cudaEventCreateWithFlags(&evF, cudaEventDisableTiming);
        cudaEventCreateWithFlags(&evB, cudaEventDisableTiming);
        cudaEventCreateWithFlags(&evJ, cudaEventDisableTiming);
        init_done = true;
    }

    // prep (zero + wprep fused) on stream 0
    prep_kernel<<<(N + 255) / 256, 256>>>(W, N);

    // fork
    cudaEventRecord(evF, 0);
    cudaStreamWaitEvent(s1, evF, 0);

    // branch A (s1): GEMM
    gemm_mma<<<(N + BM - 1) / BM, 128, GEMM_SMEM, s1>>>(X, bias, N);

    // branch B (stream 0): fill
    {
        int nthreads = (E + 3) / 4;
        fill_kernel<<<(nthreads + 255) / 256, 256>>>(src, dst, E, N);
    }
    cudaEventRecord(evB, 0);

    // msg on s1 after gemm (s1 order) and fill (evB)
    cudaStreamWaitEvent(s1, evB, 0);
    {
        int total = N * (CDIM / 4);
        msg_kernel<<<(total + 255) / 256, 256, 0, s1>>>(N);
    }
    cudaEventRecord(evJ, s1);

    // gather on stream 0 after msg
    cudaStreamWaitEvent(0, evJ, 0);
    {
        long long threads = (long long)N * 32;
        int blocks = (int)((threads + 255) / 256);
        gather_kernel<<<blocks, 256>>>(out, N);
    }
}

// round 14
// speedup vs baseline: 1.1042x; 1.1042x over previous
#include <cuda_runtime.h>
#include <cuda_bf16.h>
#include <cuda_fp16.h>
#include <stdint.h>

#define NMAX 100032
#define FDIM 512
#define CDIM 64
#define ALPHA 0.2f
#define BCAP 128

__device__ __align__(256) float  g_h0   [(size_t)NMAX * CDIM];
__device__ __align__(256) __half g_msg16[(size_t)NMAX * CDIM];
__device__ int   g_cnt_in[NMAX];
__device__ int   g_cnt_out[NMAX];
__device__ __align__(16) int g_ebuf[(size_t)NMAX * BCAP];

__device__ __align__(16) uint16_t g_wb_hi[8 * 64 * 72];
__device__ __align__(16) uint16_t g_wb_lo[8 * 64 * 72];

// ---------------------------------------------------------------------------
// helpers
// ---------------------------------------------------------------------------
__device__ __forceinline__ uint32_t smem_u32(const void* p) {
    uint32_t a;
    asm("{ .reg .u64 t; cvta.to.shared.u64 t, %1; cvt.u32.u64 %0, t; }"
        : "=r"(a) : "l"(p));
    return a;
}
__device__ __forceinline__ float trunc_bf(float x) {
    return __uint_as_float(__float_as_uint(x) & 0xFFFF0000u);
}
__device__ __forceinline__ uint32_t pack_lo2(float e0, float e1) {
    float r0 = e0 - trunc_bf(e0);
    float r1 = e1 - trunc_bf(e1);
    uint32_t d;
    asm("cvt.rn.bf16x2.f32 %0, %1, %2;" : "=r"(d) : "f"(r1), "f"(r0));
    return d;
}
__device__ __forceinline__ void mma_bf16(float* d, const uint32_t* a,
                                         uint32_t b0, uint32_t b1) {
    asm volatile(
        "mma.sync.aligned.m16n8k16.row.col.f32.bf16.bf16.f32 "
        "{%0,%1,%2,%3}, {%4,%5,%6,%7}, {%8,%9}, {%0,%1,%2,%3};"
        : "+f"(d[0]), "+f"(d[1]), "+f"(d[2]), "+f"(d[3])
        : "r"(a[0]), "r"(a[1]), "r"(a[2]), "r"(a[3]), "r"(b0), "r"(b1));
}
__device__ __forceinline__ void cp_async16(uint32_t dst, const void* src) {
    asm volatile("cp.async.ca.shared.global [%0], [%1], 16;"
                 :: "r"(dst), "l"(src) : "memory");
}

// ---------------------------------------------------------------------------
// 1) prep: zero counters + W -> bf16 hi/lo fragment images (fused)
// ---------------------------------------------------------------------------
__global__ void prep_kernel(const float* __restrict__ W, int N) {
    int idx = blockIdx.x * blockDim.x + threadIdx.x;
    if (idx < N) { g_cnt_in[idx] = 0; g_cnt_out[idx] = 0; }
    if (idx < CDIM * FDIM) {
        int n = idx >> 9;
        int k = idx & 511;
        float w = W[idx];
        uint32_t wb = __float_as_uint(w);
        uint16_t hi = (uint16_t)(wb >> 16);
        float lo = w - __uint_as_float(wb & 0xFFFF0000u);
        __nv_bfloat16 lob = __float2bfloat16_rn(lo);

        int ch = k >> 6;
        int kl = k & 63;
        int ks = kl >> 4;
        int jj = kl & 15;
        int p = (jj < 8) ? ((jj >> 1) * 4 + (jj & 1))
                         : (((jj - 8) >> 1) * 4 + 2 + (jj & 1));
        int off = ch * (64 * 72) + n * 72 + ks * 16 + p;
        g_wb_hi[off] = hi;
        g_wb_lo[off] = *reinterpret_cast<uint16_t*>(&lob);
    }
}

// ---------------------------------------------------------------------------
// 2) fill: both degrees + bucket by dst (R10 exact: 1 edge/thread)
// ---------------------------------------------------------------------------
__global__ void fill_kernel(const int* __restrict__ src,
                            const int* __restrict__ dst, int E, int N) {
    int e = blockIdx.x * blockDim.x + threadIdx.x;
    if (e >= E) return;
    int s = src[e];
    int d = dst[e];
    if ((unsigned)s >= (unsigned)N || (unsigned)d >= (unsigned)N) return;
    atomicAdd(&g_cnt_out[s], 1);
    int pos = atomicAdd(&g_cnt_in[d], 1);
    if (pos < BCAP) g_ebuf[(size_t)d * BCAP + pos] = s;
}

// ---------------------------------------------------------------------------
// 3) mma.sync GEMM (R10 exact: BM=128, occ 2): h0 = X@W^T + b
// ---------------------------------------------------------------------------
#define BM 128
#define A_STRIDE_B 288
#define B_STRIDE_B 144
#define A_BUF_B 36864
#define B_BUF_B 18432
#define GEMM_SMEM 110592

__device__ __forceinline__ void issue_chunk(char* smem, const float* X,
                                            int brow, int N, int ch, int buf,
                                            int tid) {
    char* adst = smem + buf * A_BUF_B;
    int k0 = ch * 64;
#pragma unroll
    for (int i = 0; i < 16; i++) {
        int q = tid + i * 128;
        int r = q >> 4, s = q & 15;
        int row = brow + r;
        if (row >= N) row = N - 1;
        const float* src = X + (size_t)row * FDIM + k0 + s * 4;
        cp_async16(smem_u32(adst + r * A_STRIDE_B + s * 16), src);
    }
    const char* bsrc_h = reinterpret_cast<const char*>(g_wb_hi) + ch * 9216;
    const char* bsrc_l = reinterpret_cast<const char*>(g_wb_lo) + ch * 9216;
    char* bh = smem + 73728 + buf * B_BUF_B;
    char* bl = bh + 9216;
#pragma unroll
    for (int i = 0; i < 5; i++) {
        int q = tid + i * 128;
        if (q < 576) {
            cp_async16(smem_u32(bh + q * 16), bsrc_h + q * 16);
            cp_async16(smem_u32(bl + q * 16), bsrc_l + q * 16);
        }
    }
}

__global__ __launch_bounds__(128, 2)
void gemm_mma(const float* __restrict__ X, const float* __restrict__ bias, int N) {
    extern __shared__ __align__(16) char smem[];
    __shared__ float s_bias[CDIM];

    int tid = threadIdx.x;
    int wid = tid >> 5;
    int lane = tid & 31;
    int gr = lane >> 2;
    int tg = lane & 3;
    int brow = blockIdx.x * BM;

    if (tid < CDIM) s_bias[tid] = bias[tid];

    float acc[2][8][4];
#pragma unroll
    for (int m = 0; m < 2; m++)
#pragma unroll
        for (int t = 0; t < 8; t++)
#pragma unroll
            for (int j = 0; j < 4; j++) acc[m][t][j] = 0.f;

    issue_chunk(smem, X, brow, N, 0, 0, tid);
    asm volatile("cp.async.commit_group;" ::: "memory");
    issue_chunk(smem, X, brow, N, 1, 1, tid);
    asm volatile("cp.async.commit_group;" ::: "memory");

    for (int c = 0; c < 8; c++) {
        int b = c & 1;
        asm volatile("cp.async.wait_group 1;" ::: "memory");
        __syncthreads();

        const char* ab = smem + b * A_BUF_B;
        const char* bh = smem + 73728 + b * B_BUF_B;
        const char* bl = bh + 9216;

#pragma unroll
        for (int ks = 0; ks < 4; ks++) {
            uint32_t ah[2][4], al[2][4];
#pragma unroll
            for (int m = 0; m < 2; m++) {
                int r0 = wid * 32 + m * 16 + gr;
                const char* base = ab + r0 * A_STRIDE_B + (ks * 16 + tg * 2) * 4;
                float2 x00 = *reinterpret_cast<const float2*>(base);
                float2 x01 = *reinterpret_cast<const float2*>(base + 32);
                float2 x10 = *reinterpret_cast<const float2*>(base + 8 * A_STRIDE_B);
                float2 x11 = *reinterpret_cast<const float2*>(base + 8 * A_STRIDE_B + 32);
                ah[m][0] = __byte_perm(__float_as_uint(x00.x), __float_as_uint(x00.y), 0x7632);
                ah[m][1] = __byte_perm(__float_as_uint(x10.x), __float_as_uint(x10.y), 0x7632);
                ah[m][2] = __byte_perm(__float_as_uint(x01.x), __float_as_uint(x01.y), 0x7632);
                ah[m][3] = __byte_perm(__float_as_uint(x11.x), __float_as_uint(x11.y), 0x7632);
                al[m][0] = pack_lo2(x00.x, x00.y);
                al[m][1] = pack_lo2(x10.x, x10.y);
                al[m][2] = pack_lo2(x01.x, x01.y);
                al[m][3] = pack_lo2(x11.x, x11.y);
            }
#pragma unroll
            for (int t = 0; t < 8; t++) {
                int n = t * 8 + gr;
                const char* bp = bh + n * B_STRIDE_B + ks * 32 + tg * 8;
                const char* lp = bl + n * B_STRIDE_B + ks * 32 + tg * 8;
                uint2 bhv = *reinterpret_cast<const uint2*>(bp);
                uint2 blv = *reinterpret_cast<const uint2*>(lp);
#pragma unroll
                for (int m = 0; m < 2; m++) {
                    mma_bf16(acc[m][t], ah[m], bhv.x, bhv.y);
                    mma_bf16(acc[m][t], ah[m], blv.x, blv.y);
                    mma_bf16(acc[m][t], al[m], bhv.x, bhv.y);
                }
            }
        }
        __syncthreads();
        if (c + 2 < 8) issue_chunk(smem, X, brow, N, c + 2, b, tid);
        asm volatile("cp.async.commit_group;" ::: "memory");
    }

#pragma unroll
    for (int m = 0; m < 2; m++) {
        int row0 = brow + wid * 32 + m * 16 + gr;
        int row1 = row0 + 8;
#pragma unroll
        for (int t = 0; t < 8; t++) {
            int col = t * 8 + tg * 2;
            float b0 = s_bias[col], b1 = s_bias[col + 1];
            if (row0 < N) {
                *reinterpret_cast<float2*>(g_h0 + (size_t)row0 * CDIM + col) =
                    make_float2(acc[m][t][0] + b0, acc[m][t][1] + b1);
            }
            if (row1 < N) {
                *reinterpret_cast<float2*>(g_h0 + (size_t)row1 * CDIM + col) =
                    make_float2(acc[m][t][2] + b0, acc[m][t][3] + b1);
            }
        }
    }
}

// ---------------------------------------------------------------------------
// 4) msg16 = fp16(h0 * rsqrt(max(cnt_out,1)))   (norm folded in)
// ---------------------------------------------------------------------------
__global__ void msg_kernel(int N) {
    int i = blockIdx.x * blockDim.x + threadIdx.x;
    int total = N * (CDIM / 4);
    if (i >= total) return;
    float ns = rsqrtf(fmaxf((float)g_cnt_out[i >> 4], 1.0f));
    float4 h = reinterpret_cast<const float4*>(g_h0)[i];
    __half2 p0 = __floats2half2_rn(h.x * ns, h.y * ns);
    __half2 p1 = __floats2half2_rn(h.z * ns, h.w * ns);
    uint2 v;
    v.x = *reinterpret_cast<uint32_t*>(&p0);
    v.y = *reinterpret_cast<uint32_t*>(&p1);
    reinterpret_cast<uint2*>(g_msg16)[i] = v;
}

// ---------------------------------------------------------------------------
// 5) gather + blend: warp per dst node (R10 exact)
// ---------------------------------------------------------------------------
__global__ __launch_bounds__(256)
void gather_kernel(float* __restrict__ out, int N) {
    int gw = (blockIdx.x * blockDim.x + threadIdx.x) >> 5;
    if (gw >= N) return;
    int lane = threadIdx.x & 31;

    int cnt = g_cnt_in[gw];
    int m_tot = cnt < BCAP ? cnt : BCAP;
    const int* bucket = g_ebuf + (size_t)gw * BCAP;
    int co = lane * 2;

    float a0x = 0.f, a0y = 0.f, a1x = 0.f, a1y = 0.f;
    float a2x = 0.f, a2y = 0.f, a3x = 0.f, a3y = 0.f;

    for (int j0 = 0; j0 < m_tot; j0 += 32) {
        int m = m_tot - j0;
        if (m > 32) m = 32;
        int myidx = 0;
        if (lane < m) myidx = __ldg(&bucket[j0 + lane]);

        int jj = 0;
        for (; jj + 8 <= m; jj += 8) {
            int i0 = __shfl_sync(~0u, myidx, jj + 0);
            int i1 = __shfl_sync(~0u, myidx, jj + 1);
            int i2 = __shfl_sync(~0u, myidx, jj + 2);
            int i3 = __shfl_sync(~0u, myidx, jj + 3);
            int i4 = __shfl_sync(~0u, myidx, jj + 4);
            int i5 = __shfl_sync(~0u, myidx, jj + 5);
            int i6 = __shfl_sync(~0u, myidx, jj + 6);
            int i7 = __shfl_sync(~0u, myidx, jj + 7);
            __half2 h0 = *reinterpret_cast<const __half2*>(g_msg16 + (size_t)i0 * CDIM + co);
            __half2 h1 = *reinterpret_cast<const __half2*>(g_msg16 + (size_t)i1 * CDIM + co);
            __half2 h2 = *reinterpret_cast<const __half2*>(g_msg16 + (size_t)i2 * CDIM + co);
            __half2 h3 = *reinterpret_cast<const __half2*>(g_msg16 + (size_t)i3 * CDIM + co);
            __half2 h4 = *reinterpret_cast<const __half2*>(g_msg16 + (size_t)i4 * CDIM + co);
            __half2 h5 = *reinterpret_cast<const __half2*>(g_msg16 + (size_t)i5 * CDIM + co);
            __half2 h6 = *reinterpret_cast<const __half2*>(g_msg16 + (size_t)i6 * CDIM + co);
            __half2 h7 = *reinterpret_cast<const __half2*>(g_msg16 + (size_t)i7 * CDIM + co);
            float2 v0 = __half22float2(h0), v1 = __half22float2(h1);
            float2 v2 = __half22float2(h2), v3 = __half22float2(h3);
            float2 v4 = __half22float2(h4), v5 = __half22float2(h5);
            float2 v6 = __half22float2(h6), v7 = __half22float2(h7);
            a0x += v0.x; a0y += v0.y; a1x += v1.x; a1y += v1.y;
            a2x += v2.x; a2y += v2.y; a3x += v3.x; a3y += v3.y;
            a0x += v4.x; a0y += v4.y; a1x += v5.x; a1y += v5.y;
            a2x += v6.x; a2y += v6.y; a3x += v7.x; a3y += v7.y;
        }
        for (; jj < m; jj++) {
            int i0 = __shfl_sync(~0u, myidx, jj);
            float2 v = __half22float2(
                *reinterpret_cast<const __half2*>(g_msg16 + (size_t)i0 * CDIM + co));
            a0x += v.x; a0y += v.y;
        }
    }
    float sx = (a0x + a1x) + (a2x + a3x);
    float sy = (a0y + a1y) + (a2y + a3y);

    float ndv = rsqrtf(fmaxf((float)cnt, 1.0f));
    float2 h = *reinterpret_cast<const float2*>(g_h0 + (size_t)gw * CDIM + co);
    float2 r;
    r.x = (1.0f - ALPHA) * ndv * sx + ALPHA * h.x;
    r.y = (1.0f - ALPHA) * ndv * sy + ALPHA * h.y;
    *reinterpret_cast<float2*>(out + (size_t)gw * CDIM + co) = r;
}

// ---------------------------------------------------------------------------
// launch (R10 topology; norm removed, zero+wprep fused)
// ---------------------------------------------------------------------------
extern "C" void kernel_launch(void* const* d_in, const int* in_sizes, int n_in,
                              void* d_out, int out_size) {
    const float* X    = (const float*)d_in[0];
    const float* W    = (const float*)d_in[1];
    const float* bias = (const float*)d_in[2];
    const int*   src  = (const int*)d_in[3];
    const int*   dst  = (const int*)d_in[4];

    int N = in_sizes[0] / FDIM;
    int E = in_sizes[3];
    float* out = (float*)d_out;

    static cudaStream_t s1 = nullptr;
    static cudaEvent_t evF = nullptr, evB = nullptr, evJ = nullptr;
    static bool init_done = false;
    if (!init_done) {
        cudaFuncSetAttribute(gemm_mma, cudaFuncAttributeMaxDynamicSharedMemorySize,
                             GEMM_SMEM);
        cudaStreamCreateWithFlags(&s1, cudaStreamNonBlocking);
        cudaEventCreateWithFlags(&evF, cudaEventDisableTiming);
        cudaEventCreateWithFlags(&evB, cudaEventDisableTiming);
        cudaEventCreateWithFlags(&evJ, cudaEventDisableTiming);
        init_done = true;
    }

    // prep (zero + wprep fused) on stream 0
    prep_kernel<<<(N + 255) / 256, 256>>>(W, N);

    // fork
    cudaEventRecord(evF, 0);
    cudaStreamWaitEvent(s1, evF, 0);

    // branch A (s1): GEMM
    gemm_mma<<<(N + BM - 1) / BM, 128, GEMM_SMEM, s1>>>(X, bias, N);

    // branch B (stream 0): fill
    fill_kernel<<<(E + 255) / 256, 256>>>(src, dst, E, N);
    cudaEventRecord(evB, 0);

    // msg on s1 after gemm (s1 order) and fill (evB)
    cudaStreamWaitEvent(s1, evB, 0);
    {
        int total = N * (CDIM / 4);
        msg_kernel<<<(total + 255) / 256, 256, 0, s1>>>(N);
    }
    cudaEventRecord(evJ, s1);

    // gather on stream 0 after msg
    cudaStreamWaitEvent(0, evJ, 0);
    {
        long long threads = (long long)N * 32;
        int blocks = (int)((threads + 255) / 256);
        gather_kernel<<<blocks, 256>>>(out, N);
    }
}